// round 1
// baseline (speedup 1.0000x reference)
#include <cuda_runtime.h>
#include <cstddef>

#define NN 65536
#define DD 512
#define KK 256
#define OO 512
#define DEG 8

#define BM 128
#define BN 128
#define BKC 16
#define PADW 132
#define NTHR 256

// 64 MB scratch for out8 [N, K] (device global: allocation-free)
__device__ float g_out8[(size_t)NN * KK];

typedef unsigned long long ull;

__device__ __forceinline__ ull pack2(float lo, float hi) {
    ull r; asm("mov.b64 %0, {%1, %2};" : "=l"(r) : "f"(lo), "f"(hi)); return r;
}
__device__ __forceinline__ ull fma2(ull a, ull b, ull c) {
    ull d; asm("fma.rn.f32x2 %0, %1, %2, %3;" : "=l"(d) : "l"(a), "l"(b), "l"(c)); return d;
}
__device__ __forceinline__ float2 unpack2(ull v) {
    float2 r; asm("mov.b64 {%0, %1}, %2;" : "=f"(r.x), "=f"(r.y) : "l"(v)); return r;
}

// ---------------------------------------------------------------------------
// Kernel 1: fused polynomial recurrence.
// Each CTA: rows [row0, row0+128), K-cols [k0, k0+128).
// For n = 1..8: G_n tile = z_tile @ T[n-1]_tile^T (D=512 reduction),
// then cur = a*G_n*prev1 - b*prev2 pointwise. prev1/prev2 in smem.
// ---------------------------------------------------------------------------
__global__ void __launch_bounds__(NTHR, 1)
poly_kernel(const float* __restrict__ z, const float* __restrict__ T0,
            const float* __restrict__ T)
{
    extern __shared__ float sm[];
    float*  zs  = sm;                              // [BKC][PADW]
    float*  ts  = sm + BKC * PADW;                 // [BKC][PADW]
    float2* p1v = (float2*)(sm + 2 * BKC * PADW);  // 8192 float2
    float2* p2v = p1v + (BM * BN / 2);             // 8192 float2

    const int tid  = threadIdx.x;
    const int tx   = tid & 15;
    const int ty   = tid >> 4;
    const int row0 = blockIdx.y * BM;
    const int k0   = blockIdx.x * BN;

    // prev2 init = T0[k] broadcast over rows (degree 0)
    #pragma unroll
    for (int jp = 0; jp < 4; jp++) {
        float2 t0v = *(const float2*)&T0[k0 + tx * 8 + jp * 2];
        #pragma unroll
        for (int i = 0; i < 8; i++) p2v[(i * 4 + jp) * NTHR + tid] = t0v;
    }

    for (int n = 1; n <= DEG; n++) {
        ull acc[8][4];
        #pragma unroll
        for (int i = 0; i < 8; i++)
            #pragma unroll
            for (int jp = 0; jp < 4; jp++) acc[i][jp] = 0ULL;

        const float* Tn = T + (size_t)(n - 1) * KK * DD;

        // prefetch chunk 0 into registers
        float4 rz[2], rt[2];
        #pragma unroll
        for (int p = 0; p < 2; p++) {
            int e = tid + p * NTHR;
            int r = e >> 2, dg = (e & 3) * 4;
            rz[p] = *(const float4*)&z [(size_t)(row0 + r) * DD + dg];
            rt[p] = *(const float4*)&Tn[(size_t)(k0   + r) * DD + dg];
        }

        for (int c = 0; c < DD / BKC; c++) {
            __syncthreads();
            #pragma unroll
            for (int p = 0; p < 2; p++) {
                int e = tid + p * NTHR;
                int r = e >> 2, dg = (e & 3) * 4;
                zs[(dg + 0) * PADW + r] = rz[p].x;
                zs[(dg + 1) * PADW + r] = rz[p].y;
                zs[(dg + 2) * PADW + r] = rz[p].z;
                zs[(dg + 3) * PADW + r] = rz[p].w;
                ts[(dg + 0) * PADW + r] = rt[p].x;
                ts[(dg + 1) * PADW + r] = rt[p].y;
                ts[(dg + 2) * PADW + r] = rt[p].z;
                ts[(dg + 3) * PADW + r] = rt[p].w;
            }
            __syncthreads();
            if (c + 1 < DD / BKC) {
                int d0 = (c + 1) * BKC;
                #pragma unroll
                for (int p = 0; p < 2; p++) {
                    int e = tid + p * NTHR;
                    int r = e >> 2, dg = (e & 3) * 4;
                    rz[p] = *(const float4*)&z [(size_t)(row0 + r) * DD + d0 + dg];
                    rt[p] = *(const float4*)&Tn[(size_t)(k0   + r) * DD + d0 + dg];
                }
            }
            #pragma unroll
            for (int kk = 0; kk < BKC; kk++) {
                const float* za = &zs[kk * PADW + ty * 8];
                float4 a0 = *(const float4*)za;
                float4 a1 = *(const float4*)(za + 4);
                const float* tb = &ts[kk * PADW + tx * 8];
                float4 b0 = *(const float4*)tb;
                float4 b1 = *(const float4*)(tb + 4);
                ull bp0 = pack2(b0.x, b0.y), bp1 = pack2(b0.z, b0.w);
                ull bp2 = pack2(b1.x, b1.y), bp3 = pack2(b1.z, b1.w);
                float ar[8] = {a0.x, a0.y, a0.z, a0.w, a1.x, a1.y, a1.z, a1.w};
                #pragma unroll
                for (int i = 0; i < 8; i++) {
                    ull ad = pack2(ar[i], ar[i]);
                    acc[i][0] = fma2(ad, bp0, acc[i][0]);
                    acc[i][1] = fma2(ad, bp1, acc[i][1]);
                    acc[i][2] = fma2(ad, bp2, acc[i][2]);
                    acc[i][3] = fma2(ad, bp3, acc[i][3]);
                }
            }
        }

        // recurrence update (thread-private smem slots, no sync needed)
        if (n == 1) {
            #pragma unroll
            for (int i = 0; i < 8; i++)
                #pragma unroll
                for (int jp = 0; jp < 4; jp++)
                    p1v[(i * 4 + jp) * NTHR + tid] = unpack2(acc[i][jp]);
        } else {
            float fa = (2.0f * n - 1.0f) / n;
            float fb = (n - 1.0f) / n;
            #pragma unroll
            for (int i = 0; i < 8; i++)
                #pragma unroll
                for (int jp = 0; jp < 4; jp++) {
                    int idx = (i * 4 + jp) * NTHR + tid;
                    float2 g  = unpack2(acc[i][jp]);
                    float2 q1 = p1v[idx];
                    float2 q2 = p2v[idx];
                    float2 cur;
                    cur.x = fa * g.x * q1.x - fb * q2.x;
                    cur.y = fa * g.y * q1.y - fb * q2.y;
                    p2v[idx] = q1;
                    p1v[idx] = cur;
                }
        }
    }

    // write out8 tile
    #pragma unroll
    for (int i = 0; i < 8; i++) {
        size_t gr = (size_t)(row0 + ty * 8 + i);
        #pragma unroll
        for (int jp = 0; jp < 4; jp++) {
            *(float2*)&g_out8[gr * KK + k0 + tx * 8 + jp * 2] =
                p1v[(i * 4 + jp) * NTHR + tid];
        }
    }
}

// ---------------------------------------------------------------------------
// Kernel 2: out = out8 [N,256] @ C_w^T [256,512] + C_b
// ---------------------------------------------------------------------------
__global__ void __launch_bounds__(NTHR, 2)
cgemm_kernel(const float* __restrict__ Cw, const float* __restrict__ Cb,
             float* __restrict__ out)
{
    __shared__ float zs[BKC * PADW];
    __shared__ float ts[BKC * PADW];

    const int tid  = threadIdx.x;
    const int tx   = tid & 15;
    const int ty   = tid >> 4;
    const int row0 = blockIdx.y * BM;
    const int o0   = blockIdx.x * BN;

    ull acc[8][4];
    #pragma unroll
    for (int i = 0; i < 8; i++)
        #pragma unroll
        for (int jp = 0; jp < 4; jp++) acc[i][jp] = 0ULL;

    const float* A = g_out8;

    float4 rz[2], rt[2];
    #pragma unroll
    for (int p = 0; p < 2; p++) {
        int e = tid + p * NTHR;
        int r = e >> 2, dg = (e & 3) * 4;
        rz[p] = *(const float4*)&A [(size_t)(row0 + r) * KK + dg];
        rt[p] = *(const float4*)&Cw[(size_t)(o0   + r) * KK + dg];
    }

    for (int c = 0; c < KK / BKC; c++) {
        __syncthreads();
        #pragma unroll
        for (int p = 0; p < 2; p++) {
            int e = tid + p * NTHR;
            int r = e >> 2, dg = (e & 3) * 4;
            zs[(dg + 0) * PADW + r] = rz[p].x;
            zs[(dg + 1) * PADW + r] = rz[p].y;
            zs[(dg + 2) * PADW + r] = rz[p].z;
            zs[(dg + 3) * PADW + r] = rz[p].w;
            ts[(dg + 0) * PADW + r] = rt[p].x;
            ts[(dg + 1) * PADW + r] = rt[p].y;
            ts[(dg + 2) * PADW + r] = rt[p].z;
            ts[(dg + 3) * PADW + r] = rt[p].w;
        }
        __syncthreads();
        if (c + 1 < KK / BKC) {
            int d0 = (c + 1) * BKC;
            #pragma unroll
            for (int p = 0; p < 2; p++) {
                int e = tid + p * NTHR;
                int r = e >> 2, dg = (e & 3) * 4;
                rz[p] = *(const float4*)&A [(size_t)(row0 + r) * KK + d0 + dg];
                rt[p] = *(const float4*)&Cw[(size_t)(o0   + r) * KK + d0 + dg];
            }
        }
        #pragma unroll
        for (int kk = 0; kk < BKC; kk++) {
            const float* za = &zs[kk * PADW + ty * 8];
            float4 a0 = *(const float4*)za;
            float4 a1 = *(const float4*)(za + 4);
            const float* tb = &ts[kk * PADW + tx * 8];
            float4 b0 = *(const float4*)tb;
            float4 b1 = *(const float4*)(tb + 4);
            ull bp0 = pack2(b0.x, b0.y), bp1 = pack2(b0.z, b0.w);
            ull bp2 = pack2(b1.x, b1.y), bp3 = pack2(b1.z, b1.w);
            float ar[8] = {a0.x, a0.y, a0.z, a0.w, a1.x, a1.y, a1.z, a1.w};
            #pragma unroll
            for (int i = 0; i < 8; i++) {
                ull ad = pack2(ar[i], ar[i]);
                acc[i][0] = fma2(ad, bp0, acc[i][0]);
                acc[i][1] = fma2(ad, bp1, acc[i][1]);
                acc[i][2] = fma2(ad, bp2, acc[i][2]);
                acc[i][3] = fma2(ad, bp3, acc[i][3]);
            }
        }
    }

    #pragma unroll
    for (int i = 0; i < 8; i++) {
        size_t gr = (size_t)(row0 + ty * 8 + i);
        #pragma unroll
        for (int jp = 0; jp < 4; jp++) {
            int oc = o0 + tx * 8 + jp * 2;
            float2 g = unpack2(acc[i][jp]);
            g.x += Cb[oc];
            g.y += Cb[oc + 1];
            *(float2*)&out[gr * OO + oc] = g;
        }
    }
}

extern "C" void kernel_launch(void* const* d_in, const int* in_sizes, int n_in,
                              void* d_out, int out_size) {
    const float* z  = (const float*)d_in[0];
    const float* T0 = (const float*)d_in[1];
    const float* T  = (const float*)d_in[2];
    const float* Cw = (const float*)d_in[3];
    const float* Cb = (const float*)d_in[4];
    float* out = (float*)d_out;

    const int smem1 = (2 * BKC * PADW + 2 * BM * BN) * (int)sizeof(float); // 147968 B
    cudaFuncSetAttribute(poly_kernel, cudaFuncAttributeMaxDynamicSharedMemorySize, smem1);

    dim3 g1(KK / BN, NN / BM);   // (2, 512)
    poly_kernel<<<g1, NTHR, smem1>>>(z, T0, T);

    dim3 g2(OO / BN, NN / BM);   // (4, 512)
    cgemm_kernel<<<g2, NTHR>>>(Cw, Cb, out);
}

// round 6
// speedup vs baseline: 4.3941x; 4.3941x over previous
#include <cuda_runtime.h>
#include <cuda_bf16.h>
#include <cstdint>
#include <cstddef>

#define NN 65536
#define DD 512
#define KK 256
#define OO 512
#define DEG 8
#define NTHR 256

// ---------------- device-global scratch (allocation-free) ----------------
__device__ uint16_t g_z_hi[(size_t)NN * DD];          // 64 MB
__device__ uint16_t g_z_lo[(size_t)NN * DD];          // 64 MB
__device__ uint16_t g_T_hi[(size_t)DEG * KK * DD];    // 2 MB
__device__ uint16_t g_T_lo[(size_t)DEG * KK * DD];    // 2 MB
__device__ uint16_t g_Cw_hi[(size_t)OO * KK];         // 256 KB
__device__ uint16_t g_Cw_lo[(size_t)OO * KK];         // 256 KB
__device__ uint16_t g_o8_hi[(size_t)NN * KK];         // 32 MB
__device__ uint16_t g_o8_lo[(size_t)NN * KK];         // 32 MB

// ---------------- PTX helpers (sm_80-era only: valid on plain sm_103) ----
__device__ __forceinline__ uint32_t smem_u32(const void* p) {
    uint32_t a;
    asm("{ .reg .u64 t; cvta.to.shared.u64 t, %1; cvt.u32.u64 %0, t; }" : "=r"(a) : "l"(p));
    return a;
}
__device__ __forceinline__ void cp16(uint32_t dst, const void* src) {
    asm volatile("cp.async.cg.shared.global [%0], [%1], 16;" :: "r"(dst), "l"(src));
}
__device__ __forceinline__ void cp_commit() {
    asm volatile("cp.async.commit_group;" ::: "memory");
}
template <int N>
__device__ __forceinline__ void cp_wait() {
    asm volatile("cp.async.wait_group %0;" :: "n"(N) : "memory");
}
__device__ __forceinline__ void ldsm4(uint32_t* r, uint32_t addr) {
    asm volatile("ldmatrix.sync.aligned.m8n8.x4.shared.b16 {%0,%1,%2,%3}, [%4];"
                 : "=r"(r[0]), "=r"(r[1]), "=r"(r[2]), "=r"(r[3]) : "r"(addr));
}
__device__ __forceinline__ void mma_bf16(float* c, const uint32_t* a, uint32_t b0, uint32_t b1) {
    asm volatile(
        "mma.sync.aligned.m16n8k16.row.col.f32.bf16.bf16.f32 "
        "{%0,%1,%2,%3}, {%4,%5,%6,%7}, {%8,%9}, {%0,%1,%2,%3};"
        : "+f"(c[0]), "+f"(c[1]), "+f"(c[2]), "+f"(c[3])
        : "r"(a[0]), "r"(a[1]), "r"(a[2]), "r"(a[3]), "r"(b0), "r"(b1));
}
__device__ __forceinline__ uint32_t swz(uint32_t off) { return off ^ ((off >> 3) & 0x70); }

__device__ __forceinline__ uint16_t f2bf_bits(float x) {
    return __bfloat16_as_ushort(__float2bfloat16(x));
}
__device__ __forceinline__ float bf2f(uint16_t b) {
    return __bfloat162float(__ushort_as_bfloat16(b));
}

// load [ROWS x 64] bf16 tile -> SW128-swizzled smem (128B rows)
template <int ROWS>
__device__ __forceinline__ void load_tile(uint32_t smem_base, const uint16_t* src,
                                          size_t row_stride, int tid) {
    #pragma unroll 4
    for (int s = tid; s < ROWS * 8; s += NTHR) {
        int row = s >> 3, seg = s & 7;
        uint32_t off = (uint32_t)row * 128 + seg * 16;
        cp16(smem_base + swz(off), src + (size_t)row * row_stride + seg * 8);
    }
}

// ---------------------------------------------------------------------------
// split kernel: fp32 -> (hi, lo) bf16 pairs for z, T, Cw
// ---------------------------------------------------------------------------
__global__ void split_kernel(const float* __restrict__ z, const float* __restrict__ T,
                             const float* __restrict__ Cw) {
    const size_t gth = (size_t)blockIdx.x * blockDim.x + threadIdx.x;
    const size_t nth = (size_t)gridDim.x * blockDim.x;

    auto do_range = [&](const float* src, uint16_t* hi, uint16_t* lo, size_t n4) {
        for (size_t i = gth; i < n4; i += nth) {
            float4 v = ((const float4*)src)[i];
            uint16_t h0 = f2bf_bits(v.x), h1 = f2bf_bits(v.y);
            uint16_t h2 = f2bf_bits(v.z), h3 = f2bf_bits(v.w);
            uint16_t l0 = f2bf_bits(v.x - bf2f(h0));
            uint16_t l1 = f2bf_bits(v.y - bf2f(h1));
            uint16_t l2 = f2bf_bits(v.z - bf2f(h2));
            uint16_t l3 = f2bf_bits(v.w - bf2f(h3));
            ((uint2*)hi)[i] = make_uint2((uint32_t)h0 | ((uint32_t)h1 << 16),
                                         (uint32_t)h2 | ((uint32_t)h3 << 16));
            ((uint2*)lo)[i] = make_uint2((uint32_t)l0 | ((uint32_t)l1 << 16),
                                         (uint32_t)l2 | ((uint32_t)l3 << 16));
        }
    };
    do_range(z,  g_z_hi,  g_z_lo,  (size_t)NN * DD / 4);
    do_range(T,  g_T_hi,  g_T_lo,  (size_t)DEG * KK * DD / 4);
    do_range(Cw, g_Cw_hi, g_Cw_lo, (size_t)OO * KK / 4);
}

// ---------------------------------------------------------------------------
// Shared MMA-core: one chunk = [128 x 64] A x [128 x 64] B^T -> accumulate.
// Stage layout (64 KB): A_HI 0, A_LO 16K, B_HI 32K, B_LO 48K.
// 8 warps: wm = wid&3 (rows wm*32), wn = wid>>2 (cols wn*64).
// acc[2][8][4]: m-tile, n-tile, frag.
// ---------------------------------------------------------------------------
#define ST_AH 0
#define ST_AL 16384
#define ST_BH 32768
#define ST_BL 49152
#define ST_BYTES 65536

__device__ __forceinline__ void compute_chunk(uint32_t st, float acc[2][8][4],
                                              int wr, int wc, int lane) {
    const int l15 = lane & 15;
    const int lk  = (lane >> 4) << 4;      // 0 or 16
    #pragma unroll
    for (int ks = 0; ks < 4; ks++) {
        const uint32_t kb = ks * 32 + lk;
        uint32_t ah[2][4], al[2][4], bh[4][4], bl[4][4];
        #pragma unroll
        for (int mt = 0; mt < 2; mt++)
            ldsm4(ah[mt], st + ST_AH + swz((uint32_t)(wr + mt * 16 + l15) * 128 + kb));
        #pragma unroll
        for (int ng = 0; ng < 4; ng++)
            ldsm4(bh[ng], st + ST_BH + swz((uint32_t)(wc + ng * 16 + l15) * 128 + kb));
        // hi * hi
        #pragma unroll
        for (int mt = 0; mt < 2; mt++)
            #pragma unroll
            for (int ng = 0; ng < 4; ng++) {
                mma_bf16(acc[mt][2 * ng],     ah[mt], bh[ng][0], bh[ng][2]);
                mma_bf16(acc[mt][2 * ng + 1], ah[mt], bh[ng][1], bh[ng][3]);
            }
        #pragma unroll
        for (int mt = 0; mt < 2; mt++)
            ldsm4(al[mt], st + ST_AL + swz((uint32_t)(wr + mt * 16 + l15) * 128 + kb));
        // lo * hi
        #pragma unroll
        for (int mt = 0; mt < 2; mt++)
            #pragma unroll
            for (int ng = 0; ng < 4; ng++) {
                mma_bf16(acc[mt][2 * ng],     al[mt], bh[ng][0], bh[ng][2]);
                mma_bf16(acc[mt][2 * ng + 1], al[mt], bh[ng][1], bh[ng][3]);
            }
        #pragma unroll
        for (int ng = 0; ng < 4; ng++)
            ldsm4(bl[ng], st + ST_BL + swz((uint32_t)(wc + ng * 16 + l15) * 128 + kb));
        // hi * lo
        #pragma unroll
        for (int mt = 0; mt < 2; mt++)
            #pragma unroll
            for (int ng = 0; ng < 4; ng++) {
                mma_bf16(acc[mt][2 * ng],     ah[mt], bl[ng][0], bl[ng][2]);
                mma_bf16(acc[mt][2 * ng + 1], ah[mt], bl[ng][1], bl[ng][3]);
            }
    }
}

// ---------------------------------------------------------------------------
// poly kernel: fused Legendre recurrence.
// CTA: 128 rows x 128 K-cols. G, prev1 in registers; prev2 in padded smem.
// ---------------------------------------------------------------------------
#define P2_OFF  (2 * ST_BYTES)                       // 131072
#define P2_PITCH 132
#define P_SMEM  (P2_OFF + 128 * P2_PITCH * 4)        // 198656

__global__ void __launch_bounds__(NTHR, 1)
poly_mma_kernel(const float* __restrict__ T0) {
    extern __shared__ char smem[];
    const uint32_t sbase = smem_u32(smem);
    float* prev2 = (float*)(smem + P2_OFF);

    const int tid  = threadIdx.x;
    const int lane = tid & 31;
    const int wid  = tid >> 5;
    const int wr   = (wid & 3) * 32;   // warp row base within tile
    const int wc   = (wid >> 2) * 64;  // warp col base within tile
    const int k0   = blockIdx.x * 128;
    const int row0 = blockIdx.y * 128;

    // prev2 init = T0[k] broadcast over rows (degree 0)
    for (int i = tid; i < 128 * 128; i += NTHR) {
        int r = i >> 7, c = i & 127;
        prev2[r * P2_PITCH + c] = __ldg(&T0[k0 + c]);
    }
    __syncthreads();

    float acc[2][8][4];
    float p1[2][8][4];

    auto prefetch = [&](int stage, int n1, int j1) {
        const uint32_t st = sbase + stage * ST_BYTES;
        const int d0 = j1 * 64;
        const uint16_t* Th = g_T_hi + (size_t)(n1 - 1) * KK * DD + (size_t)k0 * DD + d0;
        const uint16_t* Tl = g_T_lo + (size_t)(n1 - 1) * KK * DD + (size_t)k0 * DD + d0;
        load_tile<128>(st + ST_AH, g_z_hi + (size_t)row0 * DD + d0, DD, tid);
        load_tile<128>(st + ST_AL, g_z_lo + (size_t)row0 * DD + d0, DD, tid);
        load_tile<128>(st + ST_BH, Th, DD, tid);
        load_tile<128>(st + ST_BL, Tl, DD, tid);
        cp_commit();
    };

    prefetch(0, 1, 0);
    int it = 0;

    for (int n = 1; n <= DEG; n++) {
        #pragma unroll
        for (int mt = 0; mt < 2; mt++)
            #pragma unroll
            for (int nt = 0; nt < 8; nt++)
                #pragma unroll
                for (int f = 0; f < 4; f++) acc[mt][nt][f] = 0.0f;

        for (int j = 0; j < 8; j++) {
            const bool has_next = !(n == DEG && j == 7);
            if (has_next) {
                int j1 = j + 1, n1 = n;
                if (j1 == 8) { j1 = 0; n1 = n + 1; }
                prefetch((it + 1) & 1, n1, j1);
                cp_wait<1>();
            } else {
                cp_wait<0>();
            }
            __syncthreads();
            compute_chunk(sbase + (it & 1) * ST_BYTES, acc, wr, wc, lane);
            __syncthreads();
            it++;
        }

        // ---- recurrence epilogue for degree n (register/pointwise) ----
        const float fa = (2.0f * n - 1.0f) / n;
        const float fb = (n - 1.0f) / n;
        const int rb = wr + (lane >> 2);
        const int cb = wc + 2 * (lane & 3);
        if (n == 1) {
            #pragma unroll
            for (int mt = 0; mt < 2; mt++)
                #pragma unroll
                for (int nt = 0; nt < 8; nt++)
                    #pragma unroll
                    for (int f = 0; f < 4; f++) p1[mt][nt][f] = acc[mt][nt][f];
        } else if (n < DEG) {
            #pragma unroll
            for (int mt = 0; mt < 2; mt++)
                #pragma unroll
                for (int nt = 0; nt < 8; nt++)
                    #pragma unroll
                    for (int h = 0; h < 2; h++) {
                        const int r = rb + mt * 16 + h * 8;
                        const int c = cb + nt * 8;
                        float2 q2 = *(float2*)&prev2[r * P2_PITCH + c];
                        float g0 = acc[mt][nt][2 * h], g1 = acc[mt][nt][2 * h + 1];
                        float q10 = p1[mt][nt][2 * h], q11 = p1[mt][nt][2 * h + 1];
                        float c0 = fa * g0 * q10 - fb * q2.x;
                        float c1 = fa * g1 * q11 - fb * q2.y;
                        *(float2*)&prev2[r * P2_PITCH + c] = make_float2(q10, q11);
                        p1[mt][nt][2 * h] = c0;
                        p1[mt][nt][2 * h + 1] = c1;
                    }
        } else {
            // n == 8: cur -> out8 split bf16 hi/lo, direct to gmem
            #pragma unroll
            for (int mt = 0; mt < 2; mt++)
                #pragma unroll
                for (int nt = 0; nt < 8; nt++)
                    #pragma unroll
                    for (int h = 0; h < 2; h++) {
                        const int r = rb + mt * 16 + h * 8;
                        const int c = cb + nt * 8;
                        float2 q2 = *(float2*)&prev2[r * P2_PITCH + c];
                        float g0 = acc[mt][nt][2 * h], g1 = acc[mt][nt][2 * h + 1];
                        float c0 = fa * g0 * p1[mt][nt][2 * h]     - fb * q2.x;
                        float c1 = fa * g1 * p1[mt][nt][2 * h + 1] - fb * q2.y;
                        uint16_t h0 = f2bf_bits(c0), h1 = f2bf_bits(c1);
                        uint16_t l0 = f2bf_bits(c0 - bf2f(h0));
                        uint16_t l1 = f2bf_bits(c1 - bf2f(h1));
                        size_t idx = (size_t)(row0 + r) * KK + k0 + c;
                        *(uint32_t*)&g_o8_hi[idx] = (uint32_t)h0 | ((uint32_t)h1 << 16);
                        *(uint32_t*)&g_o8_lo[idx] = (uint32_t)l0 | ((uint32_t)l1 << 16);
                    }
        }
    }
}

// ---------------------------------------------------------------------------
// C kernel: out[N,512] = out8[N,256] @ Cw^T + Cb
// ---------------------------------------------------------------------------
#define C_SMEM (2 * ST_BYTES)

__global__ void __launch_bounds__(NTHR, 1)
cgemm_mma_kernel(const float* __restrict__ Cb, float* __restrict__ out) {
    extern __shared__ char smem[];
    const uint32_t sbase = smem_u32(smem);

    const int tid  = threadIdx.x;
    const int lane = tid & 31;
    const int wid  = tid >> 5;
    const int wr   = (wid & 3) * 32;
    const int wc   = (wid >> 2) * 64;
    const int o0   = blockIdx.x * 128;
    const int row0 = blockIdx.y * 128;

    float acc[2][8][4];
    #pragma unroll
    for (int mt = 0; mt < 2; mt++)
        #pragma unroll
        for (int nt = 0; nt < 8; nt++)
            #pragma unroll
            for (int f = 0; f < 4; f++) acc[mt][nt][f] = 0.0f;

    auto prefetch = [&](int stage, int j1) {
        const uint32_t st = sbase + stage * ST_BYTES;
        const int d0 = j1 * 64;
        load_tile<128>(st + ST_AH, g_o8_hi + (size_t)row0 * KK + d0, KK, tid);
        load_tile<128>(st + ST_AL, g_o8_lo + (size_t)row0 * KK + d0, KK, tid);
        load_tile<128>(st + ST_BH, g_Cw_hi + (size_t)o0 * KK + d0, KK, tid);
        load_tile<128>(st + ST_BL, g_Cw_lo + (size_t)o0 * KK + d0, KK, tid);
        cp_commit();
    };

    prefetch(0, 0);
    for (int j = 0; j < 4; j++) {
        if (j + 1 < 4) { prefetch((j + 1) & 1, j + 1); cp_wait<1>(); }
        else           { cp_wait<0>(); }
        __syncthreads();
        compute_chunk(sbase + (j & 1) * ST_BYTES, acc, wr, wc, lane);
        __syncthreads();
    }

    const int rb = wr + (lane >> 2);
    const int cb = wc + 2 * (lane & 3);
    #pragma unroll
    for (int nt = 0; nt < 8; nt++) {
        const int c = o0 + cb + nt * 8;
        float2 bias = *(const float2*)&Cb[c];
        #pragma unroll
        for (int mt = 0; mt < 2; mt++)
            #pragma unroll
            for (int h = 0; h < 2; h++) {
                const int r = row0 + rb + mt * 16 + h * 8;
                float2 v = make_float2(acc[mt][nt][2 * h] + bias.x,
                                       acc[mt][nt][2 * h + 1] + bias.y);
                *(float2*)&out[(size_t)r * OO + c] = v;
            }
    }
}

// ---------------------------------------------------------------------------
extern "C" void kernel_launch(void* const* d_in, const int* in_sizes, int n_in,
                              void* d_out, int out_size) {
    const float* z  = (const float*)d_in[0];
    const float* T0 = (const float*)d_in[1];
    const float* T  = (const float*)d_in[2];
    const float* Cw = (const float*)d_in[3];
    const float* Cb = (const float*)d_in[4];
    float* out = (float*)d_out;

    cudaFuncSetAttribute(poly_mma_kernel,  cudaFuncAttributeMaxDynamicSharedMemorySize, P_SMEM);
    cudaFuncSetAttribute(cgemm_mma_kernel, cudaFuncAttributeMaxDynamicSharedMemorySize, C_SMEM);

    split_kernel<<<1024, NTHR>>>(z, T, Cw);

    dim3 g1(KK / 128, NN / 128);   // (2, 512)
    poly_mma_kernel<<<g1, NTHR, P_SMEM>>>(T0);

    dim3 g2(OO / 128, NN / 128);   // (4, 512)
    cgemm_mma_kernel<<<g2, NTHR, C_SMEM>>>(Cb, out);
}